// round 5
// baseline (speedup 1.0000x reference)
#include <cuda_runtime.h>
#include <cuda_bf16.h>

// BERT embedding fused gather kernel.
// out[t, :] = token_table[seq[t]] + mean_{g<cnt} genre_table[gids[seq[t],g]] + pos_table[t % L]
//
// Layout decisions:
//  - warp per token; lane owns a float4 slice of the 128-wide embedding.
//  - genre_table (21 x 128 fp32 = 10.75 KB) staged in shared memory, accessed
//    as float4[row][32] -> conflict-free LDS.128.
//  - token_genre_ids read as two int4 (uniform address per warp -> broadcast).
//  - grid-stride loop over tokens to amortize the smem stage.

#define EMBED_VEC 32   // 128 floats = 32 float4
#define MAX_G 8

__global__ __launch_bounds__(256) void bert_embed_kernel(
    const int*    __restrict__ seq,          // [N]
    const float4* __restrict__ tok_table,    // [VOCAB][32]
    const float4* __restrict__ genre_table,  // [NG][32]
    const float4* __restrict__ pos_table,    // [MAX_LEN][32]
    const int4*   __restrict__ token_gids,   // [VOCAB][2]  (8 ints per row)
    const int*    __restrict__ genre_counts, // [VOCAB]
    float4*       __restrict__ out,          // [N][32]
    int n_tokens, int L, int n_genre_rows)
{
    // Genre table in smem: n_genre_rows (=21) rows of 32 float4.
    __shared__ float4 s_genre[21 * EMBED_VEC];

    const int n_genre_vec = n_genre_rows * EMBED_VEC;
    for (int i = threadIdx.x; i < n_genre_vec; i += blockDim.x)
        s_genre[i] = genre_table[i];
    __syncthreads();

    const int lane    = threadIdx.x & 31;
    const int warp_id = (blockIdx.x * (blockDim.x >> 5)) + (threadIdx.x >> 5);
    const int n_warps = gridDim.x * (blockDim.x >> 5);

    for (int t = warp_id; t < n_tokens; t += n_warps) {
        const int tok = __ldg(&seq[t]);
        const int l   = t % L;
        const int cnt = __ldg(&genre_counts[tok]);

        // 8 genre ids for this token (uniform across warp -> broadcast loads)
        const int4 g0 = __ldg(&token_gids[tok * 2 + 0]);
        const int4 g1 = __ldg(&token_gids[tok * 2 + 1]);
        int gid[MAX_G];
        gid[0] = g0.x; gid[1] = g0.y; gid[2] = g0.z; gid[3] = g0.w;
        gid[4] = g1.x; gid[5] = g1.y; gid[6] = g1.z; gid[7] = g1.w;

        // Issue the two big-latency loads early (independent streams).
        const float4 tv = __ldg(&tok_table[tok * EMBED_VEC + lane]);
        const float4 pv = __ldg(&pos_table[l  * EMBED_VEC + lane]);

        float4 acc = make_float4(0.f, 0.f, 0.f, 0.f);
        #pragma unroll
        for (int g = 0; g < MAX_G; g++) {
            if (g < cnt) {
                const float4 gv = s_genre[gid[g] * EMBED_VEC + lane];
                acc.x += gv.x; acc.y += gv.y; acc.z += gv.z; acc.w += gv.w;
            }
        }
        const float inv = 1.0f / (float)cnt;

        float4 o;
        o.x = tv.x + acc.x * inv + pv.x;
        o.y = tv.y + acc.y * inv + pv.y;
        o.z = tv.z + acc.z * inv + pv.z;
        o.w = tv.w + acc.w * inv + pv.w;
        out[t * EMBED_VEC + lane] = o;
    }
}

extern "C" void kernel_launch(void* const* d_in, const int* in_sizes, int n_in,
                              void* d_out, int out_size) {
    // metadata order (matches reference signature):
    //   0: sequence        int32   [B*L]        = 51200
    //   1: token_table     float32 [VOCAB*128]
    //   2: genre_table     float32 [(NG+1)*128]
    //   3: pos_table       float32 [MAX_LEN*128]
    //   4: token_genre_ids int32   [VOCAB*8]
    //   5: genre_counts    int32   [VOCAB]
    const int*    seq          = (const int*)   d_in[0];
    const float4* tok_table    = (const float4*)d_in[1];
    const float4* genre_table  = (const float4*)d_in[2];
    const float4* pos_table    = (const float4*)d_in[3];
    const int4*   token_gids   = (const int4*)  d_in[4];
    const int*    genre_counts = (const int*)   d_in[5];
    float4*       out          = (float4*)      d_out;

    const int n_tokens      = in_sizes[0];            // 51200
    const int L             = in_sizes[3] / 128;      // 200 (MAX_LEN == L here)
    const int n_genre_rows  = in_sizes[2] / 128;      // 21

    // 1280 blocks x 8 warps = 10240 warps -> ~5 tokens per warp.
    const int threads = 256;
    const int blocks  = 1280;
    bert_embed_kernel<<<blocks, threads>>>(seq, tok_table, genre_table,
                                           pos_table, token_gids, genre_counts,
                                           out, n_tokens, L, n_genre_rows);
}